// round 1
// baseline (speedup 1.0000x reference)
#include <cuda_runtime.h>
#include <math.h>

// Problem shape (fixed by the reference setup)
#define MROWS 8192
#define NCOLS 4096
#define T_ITERS 160
#define RC 32          // row chunks for X^T u partials

// ---------------- scratch (no allocations allowed) ----------------
__device__ float g_v[NCOLS];        // current Lanczos vector
__device__ float g_vprev[NCOLS];    // previous Lanczos vector
__device__ float g_u[MROWS];        // u = X v
__device__ float g_wpart[RC * NCOLS]; // partial sums of w = X^T u
__device__ float g_alpha[T_ITERS];
__device__ float g_beta[T_ITERS + 1];

// ---------------- init: deterministic pseudo-random unit vector ----------------
__global__ void k_init() {
    __shared__ float red[1024];
    int t = threadIdx.x;
    float vals[4];
    float ss = 0.f;
#pragma unroll
    for (int i = 0; i < 4; i++) {
        int j = t + i * 1024;
        unsigned h = (unsigned)j * 2654435761u;
        h ^= h >> 16; h *= 2246822519u; h ^= h >> 13;
        float x = (float)(h & 0xFFFFFF) * (1.0f / 16777216.0f) - 0.5f;
        vals[i] = x;
        ss += x * x;
    }
    red[t] = ss;
    __syncthreads();
    for (int s = 512; s > 0; s >>= 1) {
        if (t < s) red[t] += red[t + s];
        __syncthreads();
    }
    float inv = rsqrtf(red[0]);
#pragma unroll
    for (int i = 0; i < 4; i++) {
        int j = t + i * 1024;
        g_v[j] = vals[i] * inv;
        g_vprev[j] = 0.f;
    }
    if (t == 0) g_beta[0] = 0.f;
}

// ---------------- u = X v : one block per row, contiguous 16KB row read ----------------
__global__ void k_xv(const float* __restrict__ X) {
    int row = blockIdx.x;
    const float* xr = X + (size_t)row * NCOLS;
    int t = threadIdx.x;
    float acc = 0.f;
#pragma unroll
    for (int i = 0; i < NCOLS / 256; i++) {
        int j = t + i * 256;
        acc += xr[j] * g_v[j];
    }
    __shared__ float red[256];
    red[t] = acc;
    __syncthreads();
    for (int s = 128; s >= 32; s >>= 1) {
        if (t < s) red[t] += red[t + s];
        __syncthreads();
    }
    if (t < 32) {
        float v = red[t];
#pragma unroll
        for (int o = 16; o > 0; o >>= 1) v += __shfl_down_sync(0xffffffffu, v, o);
        if (t == 0) g_u[row] = v;
    }
}

// ---------------- w partials: w = X^T u ----------------
// 16 col-blocks (256 cols) x 32 row-chunks (256 rows) = 512 blocks, 256 threads.
// Coalesced across columns; u broadcast from L1/L2. Deterministic (no atomics).
__global__ void k_xtu(const float* __restrict__ X) {
    int cb = blockIdx.x & 15;
    int rc = blockIdx.x >> 4;
    int col = cb * 256 + threadIdx.x;
    int r0 = rc * (MROWS / RC);
    const float* xp = X + (size_t)r0 * NCOLS + col;
    float acc = 0.f;
#pragma unroll 8
    for (int r = 0; r < MROWS / RC; r++) {
        acc += xp[(size_t)r * NCOLS] * g_u[r0 + r];
    }
    g_wpart[rc * NCOLS + col] = acc;
}

// ---------------- Lanczos update: reduce partials, alpha, orthogonalize, beta, shift ----------------
// Single block of 1024 threads, 4 elements each. Reads 512KB of partials (L2-hot).
__global__ void k_update(int j) {
    __shared__ float red[1024];
    int t = threadIdx.x;
    float vloc[4], vp[4], wloc[4];
    float dot = 0.f;
#pragma unroll
    for (int i = 0; i < 4; i++) {
        int idx = t + i * 1024;
        float wsum = 0.f;
#pragma unroll
        for (int c = 0; c < RC; c++) wsum += g_wpart[c * NCOLS + idx];
        wloc[i] = wsum;
        vloc[i] = g_v[idx];
        vp[i]   = g_vprev[idx];
        dot += vloc[i] * wsum;
    }
    red[t] = dot;
    __syncthreads();
    for (int s = 512; s > 0; s >>= 1) {
        if (t < s) red[t] += red[t + s];
        __syncthreads();
    }
    float alpha = red[0];
    float beta_prev = g_beta[j];
    __syncthreads();   // before reusing red[]

    float ss = 0.f;
#pragma unroll
    for (int i = 0; i < 4; i++) {
        wloc[i] = wloc[i] - alpha * vloc[i] - beta_prev * vp[i];
        ss += wloc[i] * wloc[i];
    }
    red[t] = ss;
    __syncthreads();
    for (int s = 512; s > 0; s >>= 1) {
        if (t < s) red[t] += red[t + s];
        __syncthreads();
    }
    float beta = sqrtf(red[0]);
    float inv = (beta > 1e-30f) ? (1.0f / beta) : 0.0f;
#pragma unroll
    for (int i = 0; i < 4; i++) {
        int idx = t + i * 1024;
        g_vprev[idx] = vloc[i];
        g_v[idx] = wloc[i] * inv;
    }
    if (t == 0) {
        g_alpha[j] = alpha;
        g_beta[j + 1] = beta;
    }
}

// ---------------- largest eigenvalue of the tridiagonal via Sturm bisection (fp64) ----------------
__global__ void k_tridiag(float* out) {
    double a[T_ITERS], b[T_ITERS];
    for (int i = 0; i < T_ITERS; i++) {
        a[i] = (double)g_alpha[i];
        b[i] = (double)g_beta[i];   // b[i] couples rows i-1 and i (b[0] unused)
    }
    // Gershgorin bounds
    double lo = 1e300, hi = -1e300;
    for (int i = 0; i < T_ITERS; i++) {
        double r = fabs(b[i]) + ((i + 1 < T_ITERS) ? fabs(b[i + 1]) : 0.0);
        double l = a[i] - r, h = a[i] + r;
        if (l < lo) lo = l;
        if (h > hi) hi = h;
    }
    hi += 1.0;
    // bisection: smallest x such that all T eigenvalues are below x
    for (int it = 0; it < 200; it++) {
        double x = 0.5 * (lo + hi);
        int cnt = 0;
        double d = a[0] - x;
        if (d == 0.0) d = -1e-300;
        if (d < 0.0) cnt++;
        for (int i = 1; i < T_ITERS; i++) {
            d = a[i] - x - b[i] * b[i] / d;
            if (d == 0.0) d = -1e-300;
            if (d < 0.0) cnt++;
        }
        if (cnt >= T_ITERS) hi = x; else lo = x;
    }
    out[0] = (float)(0.5 * (lo + hi));   // = lambda_max(G) = sigma_1^2
}

// ---------------- launch ----------------
extern "C" void kernel_launch(void* const* d_in, const int* in_sizes, int n_in,
                              void* d_out, int out_size) {
    const float* X = (const float*)d_in[0];
    float* out = (float*)d_out;

    k_init<<<1, 1024>>>();
    for (int j = 0; j < T_ITERS; j++) {
        k_xv<<<MROWS, 256>>>(X);
        k_xtu<<<512, 256>>>(X);
        k_update<<<1, 1024>>>(j);
    }
    k_tridiag<<<1, 1>>>(out);
}

// round 2
// speedup vs baseline: 4.5307x; 4.5307x over previous
#include <cuda_runtime.h>
#include <math.h>

#define MROWS 8192
#define NCOLS 4096
#define T_ITERS 120
#define NBLK 256              // matvec blocks
#define RPB 32                // rows per matvec block
#define CHROWS 2              // rows per smem chunk
#define NCHUNK (RPB / CHROWS) // 16
#define CHUNK_FLOATS (CHROWS * NCOLS) // 8192 floats = 32KB
#define RBLK 16               // reduce blocks (= norm partials per iter)
#define SMEM_BYTES ((NCOLS + 2 * CHUNK_FLOATS) * 4) // 16KB v + 2x32KB X = 80KB

// ---------------- device scratch (no allocations allowed) ----------------
__device__ float g_y[3 * NCOLS];           // rotating unnormalized Lanczos vectors
__device__ float g_wpart[NBLK * NCOLS];    // per-block partials of w = X^T X v
__device__ float g_dot[NBLK];              // per-block partials of alpha = v^T w
__device__ float g_ss[(T_ITERS + 1) * RBLK]; // per-iter norm^2 partials of y
__device__ float g_alpha[T_ITERS];

// ---------------- init: deterministic pseudo-random unit vector ----------------
__global__ void k_init() {
    __shared__ float red[1024];
    int t = threadIdx.x;
    float vals[4];
    float ss = 0.f;
#pragma unroll
    for (int i = 0; i < 4; i++) {
        int j = t + i * 1024;
        unsigned h = (unsigned)j * 2654435761u;
        h ^= h >> 16; h *= 2246822519u; h ^= h >> 13;
        float x = (float)(h & 0xFFFFFF) * (1.0f / 16777216.0f) - 0.5f;
        vals[i] = x;
        ss += x * x;
    }
    red[t] = ss;
    __syncthreads();
    for (int s = 512; s > 0; s >>= 1) {
        if (t < s) red[t] += red[t + s];
        __syncthreads();
    }
    float inv = rsqrtf(red[0]);
#pragma unroll
    for (int i = 0; i < 4; i++) {
        int j = t + i * 1024;
        g_y[j] = vals[i] * inv;          // y_1 = v_1 (unit norm)
        g_y[2 * NCOLS + j] = 0.f;        // y_0 = 0
    }
    if (t == 0) {
#pragma unroll
        for (int p = 0; p < RBLK; p++) g_ss[p] = (p == 0) ? 1.f : 0.f; // ||y_1||^2 = 1
    }
}

// ---------------- fused matvec: w_partials = X_b^T (X_b v), one DRAM pass ----------------
__device__ __forceinline__ void prefetch_chunk(float* x_s, int buf, const float* src, int t) {
    unsigned base = (unsigned)__cvta_generic_to_shared(x_s + buf * CHUNK_FLOATS) + t * 16;
    const float4* s4 = (const float4*)src + t;
#pragma unroll
    for (int i = 0; i < 8; i++) {
        asm volatile("cp.async.cg.shared.global [%0], [%1], 16;\n"
                     :: "r"(base + i * 256 * 16), "l"(s4 + i * 256) : "memory");
    }
}

extern __shared__ float sm[];

__global__ void __launch_bounds__(256, 2) k_matvec(const float* __restrict__ X, int it) {
    float* v_s = sm;              // y (unnormalized), 4096 floats
    float* x_s = sm + NCOLS;      // 2 chunk buffers, 8192 floats each
    __shared__ float upart[8];
    __shared__ float red[256];

    int t = threadIdx.x, b = blockIdx.x;
    int lane = t & 31, w = t >> 5;

    // invn = 1/||y||   (sum 16 norm^2 partials from previous reduce / init)
    float ssum = 0.f;
#pragma unroll
    for (int p = 0; p < RBLK; p++) ssum += g_ss[it * RBLK + p];
    float invn = 1.0f / sqrtf(ssum);

    // stage y into smem
    {
        const float4* yv = (const float4*)(g_y + (it % 3) * NCOLS);
        float4* vs4 = (float4*)v_s;
#pragma unroll
        for (int i = 0; i < 4; i++) vs4[t + 256 * i] = yv[t + 256 * i];
    }

    const float* Xb = X + (size_t)b * RPB * NCOLS;
    float acc[16];
#pragma unroll
    for (int i = 0; i < 16; i++) acc[i] = 0.f;

    prefetch_chunk(x_s, 0, Xb, t);
    asm volatile("cp.async.commit_group;\n" ::: "memory");

    for (int k = 0; k < NCHUNK; k++) {
        if (k + 1 < NCHUNK) {
            prefetch_chunk(x_s, (k + 1) & 1, Xb + (k + 1) * CHUNK_FLOATS, t);
            asm volatile("cp.async.commit_group;\n" ::: "memory");
            asm volatile("cp.async.wait_group 1;\n" ::: "memory");
        } else {
            asm volatile("cp.async.wait_group 0;\n" ::: "memory");
        }
        __syncthreads();

        int buf = k & 1;
        // phase 1: u = X_chunk * y  (warp w -> row (w&1), col quarter (w>>1))
        {
            const float* xs = x_s + buf * CHUNK_FLOATS + (w & 1) * NCOLS + (w >> 1) * 1024;
            const float* vs = v_s + (w >> 1) * 1024;
            float a0 = 0.f, a1 = 0.f;
#pragma unroll
            for (int i = 0; i < 32; i += 2) {
                a0 += xs[lane + 32 * i] * vs[lane + 32 * i];
                a1 += xs[lane + 32 * (i + 1)] * vs[lane + 32 * (i + 1)];
            }
            float s = a0 + a1;
#pragma unroll
            for (int o = 16; o > 0; o >>= 1) s += __shfl_down_sync(0xffffffffu, s, o);
            if (lane == 0) upart[w] = s;
        }
        __syncthreads();

        // phase 2: w_part[c] += x[r][c] * u[r]   (u scaled by invn -> v is unit)
        {
            float u0 = invn * (upart[0] + upart[2] + upart[4] + upart[6]);
            float u1 = invn * (upart[1] + upart[3] + upart[5] + upart[7]);
            const float* x0 = x_s + buf * CHUNK_FLOATS + t;
#pragma unroll
            for (int i = 0; i < 16; i++)
                acc[i] += x0[256 * i] * u0 + x0[NCOLS + 256 * i] * u1;
        }
        __syncthreads();  // protect buffer before next prefetch overwrites it
    }

    // epilogue: write w partials + alpha partial dot(v, w_part)
    float d = 0.f;
#pragma unroll
    for (int i = 0; i < 16; i++) {
        g_wpart[(size_t)b * NCOLS + t + 256 * i] = acc[i];
        d += acc[i] * v_s[t + 256 * i];
    }
    red[t] = d;
    __syncthreads();
    for (int s = 128; s > 0; s >>= 1) {
        if (t < s) red[t] += red[t + s];
        __syncthreads();
    }
    if (t == 0) g_dot[b] = red[0] * invn;
}

// ---------------- reduce: w, alpha, orthogonalize, next y + norm partials ----------------
__global__ void k_reduce(int it) {
    __shared__ float sd[256];
    int t = threadIdx.x;
    int c = blockIdx.x * 256 + t;

    // alpha = sum of 256 dot partials (fixed order tree)
    sd[t] = g_dot[t];
    __syncthreads();
    for (int s = 128; s > 0; s >>= 1) {
        if (t < s) sd[t] += sd[t + s];
        __syncthreads();
    }
    float alpha = sd[0];
    __syncthreads();

    // norms
    float ssum = 0.f;
#pragma unroll
    for (int p = 0; p < RBLK; p++) ssum += g_ss[it * RBLK + p];
    float n = sqrtf(ssum);
    float invn = 1.0f / n;
    float bco = 0.f, invnp = 0.f;
    if (it > 0) {
        float sp = 0.f;
#pragma unroll
        for (int p = 0; p < RBLK; p++) sp += g_ss[(it - 1) * RBLK + p];
        invnp = 1.0f / sqrtf(sp);
        bco = n;                 // beta_{j-1} = ||y_j||
    }

    // w[c] = sum over 256 block partials (fixed order)
    float wv = 0.f;
    const float* wp = g_wpart + c;
#pragma unroll 8
    for (int bb = 0; bb < NBLK; bb++) wv += wp[(size_t)bb * NCOLS];

    int cur = it % 3, prev = (it + 2) % 3, nxt = (it + 1) % 3;
    float yt = wv - alpha * invn * g_y[cur * NCOLS + c]
                  - bco * invnp * g_y[prev * NCOLS + c];
    g_y[nxt * NCOLS + c] = yt;

    sd[t] = yt * yt;
    __syncthreads();
    for (int s = 128; s > 0; s >>= 1) {
        if (t < s) sd[t] += sd[t + s];
        __syncthreads();
    }
    if (t == 0) {
        g_ss[(it + 1) * RBLK + blockIdx.x] = sd[0];
        if (blockIdx.x == 0) g_alpha[it] = alpha;
    }
}

// ---------------- lambda_max of tridiagonal: warp-parallel Sturm bisection (fp64) ----------------
__global__ void k_tridiag(float* out) {
    __shared__ double a[T_ITERS], b2[T_ITERS];
    int lane = threadIdx.x;
    for (int i = lane; i < T_ITERS; i += 32) {
        a[i] = (double)g_alpha[i];
        double s = 0.0;
        if (i > 0) {
            for (int p = 0; p < RBLK; p++) s += (double)g_ss[i * RBLK + p];
        }
        b2[i] = s;  // beta_i^2 couples rows i-1, i
    }
    __syncwarp();

    // Gershgorin bounds
    double lo = 1e300, hi = -1e300;
    for (int i = lane; i < T_ITERS; i += 32) {
        double r = sqrt(b2[i]) + ((i + 1 < T_ITERS) ? sqrt(b2[i + 1]) : 0.0);
        lo = fmin(lo, a[i] - r);
        hi = fmax(hi, a[i] + r);
    }
#pragma unroll
    for (int o = 16; o > 0; o >>= 1) {
        lo = fmin(lo, __shfl_xor_sync(0xffffffffu, lo, o));
        hi = fmax(hi, __shfl_xor_sync(0xffffffffu, hi, o));
    }
    lo -= 1.0; hi += 1.0;

    // 6 rounds x 32 candidates: interval shrinks by 33x per round
    for (int round = 0; round < 6; round++) {
        double wdt = (hi - lo) / 33.0;
        double x = lo + wdt * (double)(lane + 1);
        int cnt = 0;
        double d = a[0] - x;
        if (d == 0.0) d = -1e-300;
        if (d < 0.0) cnt++;
        for (int i = 1; i < T_ITERS; i++) {
            d = a[i] - x - b2[i] / d;
            if (d == 0.0) d = -1e-300;
            if (d < 0.0) cnt++;
        }
        unsigned m = __ballot_sync(0xffffffffu, cnt >= T_ITERS);
        if (m) {
            int f = __ffs(m) - 1;       // smallest candidate with all eigs below it
            hi = lo + wdt * (double)(f + 1);
            lo = lo + wdt * (double)f;
        } else {
            lo = lo + wdt * 32.0;
        }
    }
    if (lane == 0) out[0] = (float)(0.5 * (lo + hi));  // = sigma_1^2
}

// ---------------- launch ----------------
extern "C" void kernel_launch(void* const* d_in, const int* in_sizes, int n_in,
                              void* d_out, int out_size) {
    const float* X = (const float*)d_in[0];
    float* out = (float*)d_out;

    cudaFuncSetAttribute(k_matvec, cudaFuncAttributeMaxDynamicSharedMemorySize, SMEM_BYTES);

    k_init<<<1, 1024>>>();
    for (int it = 0; it < T_ITERS; it++) {
        k_matvec<<<NBLK, 256, SMEM_BYTES>>>(X, it);
        k_reduce<<<RBLK, 256>>>(it);
    }
    k_tridiag<<<1, 32>>>(out);
}

// round 3
// speedup vs baseline: 6.8606x; 1.5142x over previous
#include <cuda_runtime.h>
#include <math.h>

#define MROWS 8192
#define NCOLS 4096
#define T_ITERS 96
#define NBLK 256               // matvec blocks
#define RPB 32                 // rows per matvec block
#define CHROWS 2               // rows per smem chunk
#define NCHUNK (RPB / CHROWS)  // 16
#define CHUNK_FLOATS (CHROWS * NCOLS)  // 8192 floats = 32KB
#define NBUF 3
#define RBLK 32                // reduce blocks (= norm partials per iter)
#define SMEM_BYTES (NBUF * CHUNK_FLOATS * 4)  // 96KB

// ---------------- device scratch ----------------
__device__ float g_y[3 * NCOLS];            // rotating unnormalized Lanczos vectors
__device__ float g_wpart[NBLK * NCOLS];     // per-block partials of w = X^T X v
__device__ float g_dot[NBLK];               // per-block partials of alpha
__device__ float g_ss[(T_ITERS + 1) * RBLK];// per-iter norm^2 partials of y
__device__ float g_alpha[T_ITERS];

// ---------------- init: deterministic pseudo-random unit vector ----------------
__global__ void k_init() {
    __shared__ float red[1024];
    int t = threadIdx.x;
    float vals[4];
    float ss = 0.f;
#pragma unroll
    for (int i = 0; i < 4; i++) {
        int j = t + i * 1024;
        unsigned h = (unsigned)j * 2654435761u;
        h ^= h >> 16; h *= 2246822519u; h ^= h >> 13;
        float x = (float)(h & 0xFFFFFF) * (1.0f / 16777216.0f) - 0.5f;
        vals[i] = x;
        ss += x * x;
    }
    red[t] = ss;
    __syncthreads();
    for (int s = 512; s > 0; s >>= 1) {
        if (t < s) red[t] += red[t + s];
        __syncthreads();
    }
    float inv = rsqrtf(red[0]);
#pragma unroll
    for (int i = 0; i < 4; i++) {
        int j = t + i * 1024;
        g_y[j] = vals[i] * inv;       // y_1 = v_1 (unit)
        g_y[2 * NCOLS + j] = 0.f;     // y_0 = 0
    }
    if (t == 0) {
#pragma unroll
        for (int p = 0; p < RBLK; p++) g_ss[p] = (p == 0) ? 1.f : 0.f;
    }
}

// ---------------- fused matvec ----------------
__device__ __forceinline__ void prefetch_chunk(float* x_s, int slot, const float* src, int t) {
    unsigned base = (unsigned)__cvta_generic_to_shared(x_s + slot * CHUNK_FLOATS) + t * 16;
    const float4* s4 = (const float4*)src + t;
#pragma unroll
    for (int i = 0; i < 8; i++) {
        asm volatile("cp.async.cg.shared.global [%0], [%1], 16;\n"
                     :: "r"(base + i * 4096), "l"(s4 + i * 256) : "memory");
    }
}

extern __shared__ float x_s[];

__global__ void __launch_bounds__(256, 2) k_matvec(const float* __restrict__ X, int it) {
    __shared__ float upart[2][8];
    __shared__ float red[256];
    int t = threadIdx.x, b = blockIdx.x;
    int lane = t & 31, w = t >> 5;

    // invn = 1/||y||
    float ssum = 0.f;
#pragma unroll
    for (int p = 0; p < RBLK; p++) ssum += g_ss[it * RBLK + p];
    float invn = 1.0f / sqrtf(ssum);

    const float4* yv = (const float4*)(g_y + (it % 3) * NCOLS);
    const float* Xb = X + (size_t)b * RPB * NCOLS;

    float4 acc4[4];
#pragma unroll
    for (int i = 0; i < 4; i++) acc4[i] = make_float4(0.f, 0.f, 0.f, 0.f);

    prefetch_chunk(x_s, 0, Xb, t);
    asm volatile("cp.async.commit_group;\n" ::: "memory");
    prefetch_chunk(x_s, 1, Xb + CHUNK_FLOATS, t);
    asm volatile("cp.async.commit_group;\n" ::: "memory");
    asm volatile("cp.async.wait_group 1;\n" ::: "memory");
    __syncthreads();  // chunk0 visible to all

    // phase1(chunk 0) -> upart[0]
    {
        const float4* xs4 = (const float4*)(x_s + (w & 1) * NCOLS) + (w >> 1) * 256;
        const float4* vs4 = yv + (w >> 1) * 256;
        float a0 = 0.f;
#pragma unroll
        for (int i = 0; i < 8; i++) {
            float4 xv4 = xs4[lane + 32 * i];
            float4 vv4 = __ldg(&vs4[lane + 32 * i]);
            a0 += xv4.x * vv4.x + xv4.y * vv4.y + xv4.z * vv4.z + xv4.w * vv4.w;
        }
#pragma unroll
        for (int o = 16; o > 0; o >>= 1) a0 += __shfl_down_sync(0xffffffffu, a0, o);
        if (lane == 0) upart[0][w] = a0;
    }

    for (int k = 0; k < NCHUNK; k++) {
        if (k + 1 < NCHUNK)
            asm volatile("cp.async.wait_group 0;\n" ::: "memory");  // chunk k+1 landed
        __syncthreads();  // chunk k+1 + upart[k&1] visible; slot (k-1)%3 free

        if (k + 2 < NCHUNK) {
            prefetch_chunk(x_s, (k + 2) % NBUF, Xb + (size_t)(k + 2) * CHUNK_FLOATS, t);
            asm volatile("cp.async.commit_group;\n" ::: "memory");
        }

        if (k + 1 < NCHUNK) {
            // phase1(chunk k+1) -> upart[(k+1)&1]
            const float4* xs4 = (const float4*)(x_s + ((k + 1) % NBUF) * CHUNK_FLOATS
                                                + (w & 1) * NCOLS) + (w >> 1) * 256;
            const float4* vs4 = yv + (w >> 1) * 256;
            float a0 = 0.f;
#pragma unroll
            for (int i = 0; i < 8; i++) {
                float4 xv4 = xs4[lane + 32 * i];
                float4 vv4 = __ldg(&vs4[lane + 32 * i]);
                a0 += xv4.x * vv4.x + xv4.y * vv4.y + xv4.z * vv4.z + xv4.w * vv4.w;
            }
#pragma unroll
            for (int o = 16; o > 0; o >>= 1) a0 += __shfl_down_sync(0xffffffffu, a0, o);
            if (lane == 0) upart[(k + 1) & 1][w] = a0;
        }

        // phase2(chunk k): acc += x_row0*u0 + x_row1*u1
        {
            float u0 = invn * (upart[k & 1][0] + upart[k & 1][2] + upart[k & 1][4] + upart[k & 1][6]);
            float u1 = invn * (upart[k & 1][1] + upart[k & 1][3] + upart[k & 1][5] + upart[k & 1][7]);
            const float4* x0 = (const float4*)(x_s + (k % NBUF) * CHUNK_FLOATS) + t;
#pragma unroll
            for (int j = 0; j < 4; j++) {
                float4 r0 = x0[256 * j];
                float4 r1 = x0[1024 + 256 * j];
                acc4[j].x += r0.x * u0 + r1.x * u1;
                acc4[j].y += r0.y * u0 + r1.y * u1;
                acc4[j].z += r0.z * u0 + r1.z * u1;
                acc4[j].w += r0.w * u0 + r1.w * u1;
            }
        }
    }

    // epilogue: write w partials + alpha partial
    float d = 0.f;
    float4* wp = (float4*)(g_wpart + (size_t)b * NCOLS);
#pragma unroll
    for (int j = 0; j < 4; j++) {
        wp[t + 256 * j] = acc4[j];
        float4 vv = __ldg(&yv[t + 256 * j]);
        d += acc4[j].x * vv.x + acc4[j].y * vv.y + acc4[j].z * vv.z + acc4[j].w * vv.w;
    }
    red[t] = d;
    __syncthreads();
    for (int s = 128; s > 0; s >>= 1) {
        if (t < s) red[t] += red[t + s];
        __syncthreads();
    }
    if (t == 0) g_dot[b] = red[0] * invn;
}

// ---------------- reduce: w, alpha, orthogonalize, next y + norm partials ----------------
__global__ void __launch_bounds__(1024) k_reduce(int it) {
    __shared__ float sa[1024];
    __shared__ float4 sp[32][32];   // [slice][col-group] 16KB
    int t = threadIdx.x;
    int lane = t & 31;
    int slice = t >> 5;                       // 0..31, 8 b-values each
    int cg = blockIdx.x * 32 + lane;          // float4 column-group, 0..1023

    // issue wpart partial-sum loads first (overlap with alpha reduce)
    float4 wsum = make_float4(0.f, 0.f, 0.f, 0.f);
    {
        const float4* wp = (const float4*)g_wpart + cg;
#pragma unroll
        for (int i = 0; i < 8; i++) {
            float4 v = wp[(size_t)(slice * 8 + i) * (NCOLS / 4)];
            wsum.x += v.x; wsum.y += v.y; wsum.z += v.z; wsum.w += v.w;
        }
    }

    // alpha = fixed-order tree over 256 dot partials
    sa[t] = (t < NBLK) ? g_dot[t] : 0.f;
    __syncthreads();
    for (int s = 512; s > 0; s >>= 1) {
        if (t < s) sa[t] += sa[t + s];
        __syncthreads();
    }
    float alpha = sa[0];

    // combine 32 slices per column-group (fixed-order tree)
    sp[slice][lane] = wsum;
    __syncthreads();
    for (int s = 16; s > 0; s >>= 1) {
        if (slice < s) {
            float4 o = sp[slice + s][lane];
            sp[slice][lane].x += o.x; sp[slice][lane].y += o.y;
            sp[slice][lane].z += o.z; sp[slice][lane].w += o.w;
        }
        __syncthreads();
    }

    if (slice == 0) {
        // norms
        float ssum = 0.f;
#pragma unroll
        for (int p = 0; p < RBLK; p++) ssum += g_ss[it * RBLK + p];
        float n = sqrtf(ssum);
        float invn = 1.0f / n;
        float bco = 0.f, invnp = 0.f;
        if (it > 0) {
            float spv = 0.f;
#pragma unroll
            for (int p = 0; p < RBLK; p++) spv += g_ss[(it - 1) * RBLK + p];
            invnp = 1.0f / sqrtf(spv);
            bco = n;
        }
        float ca = alpha * invn, cb = bco * invnp;

        float4 wv = sp[0][lane];
        const float4* ycur = (const float4*)(g_y + (it % 3) * NCOLS);
        const float4* yprv = (const float4*)(g_y + ((it + 2) % 3) * NCOLS);
        float4* ynxt = (float4*)(g_y + ((it + 1) % 3) * NCOLS);
        float4 vc = ycur[cg], vp4 = yprv[cg];
        float4 yt;
        yt.x = wv.x - ca * vc.x - cb * vp4.x;
        yt.y = wv.y - ca * vc.y - cb * vp4.y;
        yt.z = wv.z - ca * vc.z - cb * vp4.z;
        yt.w = wv.w - ca * vc.w - cb * vp4.w;
        ynxt[cg] = yt;

        float nrm = yt.x * yt.x + yt.y * yt.y + yt.z * yt.z + yt.w * yt.w;
#pragma unroll
        for (int o = 16; o > 0; o >>= 1) nrm += __shfl_down_sync(0xffffffffu, nrm, o);
        if (lane == 0) g_ss[(it + 1) * RBLK + blockIdx.x] = nrm;
        if (blockIdx.x == 0 && t == 0) g_alpha[it] = alpha;
    }
}

// ---------------- lambda_max of tridiagonal: warp-parallel Sturm bisection (fp64) ----------------
__global__ void k_tridiag(float* out) {
    __shared__ double a[T_ITERS], b2[T_ITERS];
    int lane = threadIdx.x;
    for (int i = lane; i < T_ITERS; i += 32) {
        a[i] = (double)g_alpha[i];
        double s = 0.0;
        if (i > 0) {
            for (int p = 0; p < RBLK; p++) s += (double)g_ss[i * RBLK + p];
        }
        b2[i] = s;  // beta_i^2 couples rows i-1, i
    }
    __syncwarp();

    double lo = 1e300, hi = -1e300;
    for (int i = lane; i < T_ITERS; i += 32) {
        double r = sqrt(b2[i]) + ((i + 1 < T_ITERS) ? sqrt(b2[i + 1]) : 0.0);
        lo = fmin(lo, a[i] - r);
        hi = fmax(hi, a[i] + r);
    }
#pragma unroll
    for (int o = 16; o > 0; o >>= 1) {
        lo = fmin(lo, __shfl_xor_sync(0xffffffffu, lo, o));
        hi = fmax(hi, __shfl_xor_sync(0xffffffffu, hi, o));
    }
    lo -= 1.0; hi += 1.0;

    for (int round = 0; round < 6; round++) {
        double wdt = (hi - lo) / 33.0;
        double x = lo + wdt * (double)(lane + 1);
        int cnt = 0;
        double d = a[0] - x;
        if (d == 0.0) d = -1e-300;
        if (d < 0.0) cnt++;
        for (int i = 1; i < T_ITERS; i++) {
            d = a[i] - x - b2[i] / d;
            if (d == 0.0) d = -1e-300;
            if (d < 0.0) cnt++;
        }
        unsigned m = __ballot_sync(0xffffffffu, cnt >= T_ITERS);
        if (m) {
            int f = __ffs(m) - 1;
            hi = lo + wdt * (double)(f + 1);
            lo = lo + wdt * (double)f;
        } else {
            lo = lo + wdt * 32.0;
        }
    }
    if (lane == 0) out[0] = (float)(0.5 * (lo + hi));  // sigma_1^2
}

// ---------------- launch ----------------
extern "C" void kernel_launch(void* const* d_in, const int* in_sizes, int n_in,
                              void* d_out, int out_size) {
    const float* X = (const float*)d_in[0];
    float* out = (float*)d_out;

    cudaFuncSetAttribute(k_matvec, cudaFuncAttributeMaxDynamicSharedMemorySize, SMEM_BYTES);

    k_init<<<1, 1024>>>();
    for (int it = 0; it < T_ITERS; it++) {
        k_matvec<<<NBLK, 256, SMEM_BYTES>>>(X, it);
        k_reduce<<<RBLK, 1024>>>(it);
    }
    k_tridiag<<<1, 32>>>(out);
}

// round 4
// speedup vs baseline: 9.2295x; 1.3453x over previous
#include <cuda_runtime.h>
#include <math.h>

#define MROWS 8192
#define NCOLS 4096
#define T_ITERS 72
#define NBLK 256               // matvec blocks
#define RPB 32                 // rows per matvec block
#define NCHUNK 32              // 1 row per chunk
#define CHUNK_FLOATS NCOLS     // 4096 floats = 16KB
#define NBUF 6
#define RBLK 32                // reduce blocks (= norm partials per iter)
#define SMEM_BYTES (NBUF * CHUNK_FLOATS * 4)  // 96KB

// ---------------- device scratch ----------------
__device__ float g_y[3 * NCOLS];            // rotating unnormalized Lanczos vectors
__device__ float g_wpart[NBLK * NCOLS];     // per-block partials of w = X^T X v
__device__ float g_dot[NBLK];               // per-block partials of alpha
__device__ float g_ss[(T_ITERS + 1) * RBLK];// per-iter norm^2 partials of y
__device__ float g_alpha[T_ITERS];

// ---------------- init: deterministic pseudo-random unit vector ----------------
__global__ void k_init() {
    __shared__ float red[1024];
    int t = threadIdx.x;
    float vals[4];
    float ss = 0.f;
#pragma unroll
    for (int i = 0; i < 4; i++) {
        int j = t + i * 1024;
        unsigned h = (unsigned)j * 2654435761u;
        h ^= h >> 16; h *= 2246822519u; h ^= h >> 13;
        float x = (float)(h & 0xFFFFFF) * (1.0f / 16777216.0f) - 0.5f;
        vals[i] = x;
        ss += x * x;
    }
    red[t] = ss;
    __syncthreads();
    for (int s = 512; s > 0; s >>= 1) {
        if (t < s) red[t] += red[t + s];
        __syncthreads();
    }
    float inv = rsqrtf(red[0]);
#pragma unroll
    for (int i = 0; i < 4; i++) {
        int j = t + i * 1024;
        g_y[j] = vals[i] * inv;       // y_1 = v_1 (unit)
        g_y[2 * NCOLS + j] = 0.f;     // y_0 = 0
    }
    if (t == 0) {
#pragma unroll
        for (int p = 0; p < RBLK; p++) g_ss[p] = (p == 0) ? 1.f : 0.f;
    }
}

// ---------------- fused matvec: one DRAM pass, 4 chunk-loads in flight ----------------
__device__ __forceinline__ void prefetch_chunk(float* x_s, int slot, const float* src, int t) {
    unsigned base = (unsigned)__cvta_generic_to_shared(x_s + slot * CHUNK_FLOATS) + t * 16;
    const float4* s4 = (const float4*)src + t;
#pragma unroll
    for (int i = 0; i < 4; i++) {
        asm volatile("cp.async.cg.shared.global [%0], [%1], 16;\n"
                     :: "r"(base + i * 4096), "l"(s4 + i * 256) : "memory");
    }
    asm volatile("cp.async.commit_group;\n" ::: "memory");
}

extern __shared__ float x_s[];

// phase1: warp-partial dot of chunk row with v
__device__ __forceinline__ float p1_dot(const float* xs, const float4* yv, int lane, int w) {
    const float4* xs4 = (const float4*)xs + w * 128;
    const float4* vs4 = yv + w * 128;
    float a0 = 0.f;
#pragma unroll
    for (int i = 0; i < 4; i++) {
        float4 xv4 = xs4[lane + 32 * i];
        float4 vv4 = __ldg(&vs4[lane + 32 * i]);
        a0 += xv4.x * vv4.x + xv4.y * vv4.y + xv4.z * vv4.z + xv4.w * vv4.w;
    }
#pragma unroll
    for (int o = 16; o > 0; o >>= 1) a0 += __shfl_down_sync(0xffffffffu, a0, o);
    return a0;
}

__global__ void __launch_bounds__(256, 2) k_matvec(const float* __restrict__ X, int it) {
    __shared__ float upart[2][8];
    __shared__ float red[256];
    int t = threadIdx.x, b = blockIdx.x;
    int lane = t & 31, w = t >> 5;

    // invn = 1/||y||
    float ssum = 0.f;
#pragma unroll
    for (int p = 0; p < RBLK; p++) ssum += g_ss[it * RBLK + p];
    float invn = 1.0f / sqrtf(ssum);

    const float4* yv = (const float4*)(g_y + (it % 3) * NCOLS);
    const float* Xb = X + (size_t)b * RPB * NCOLS;

    float4 acc4[4];
#pragma unroll
    for (int i = 0; i < 4; i++) acc4[i] = make_float4(0.f, 0.f, 0.f, 0.f);

    // prologue: 5 chunk loads in flight
#pragma unroll
    for (int c = 0; c < 5; c++) prefetch_chunk(x_s, c, Xb + (size_t)c * CHUNK_FLOATS, t);
    asm volatile("cp.async.wait_group 4;\n" ::: "memory");  // chunk 0 landed
    __syncthreads();
    if (lane == 0) upart[0][w] = 0.f;   // init both banks' stale guard (b0 written below)
    {
        float a0 = p1_dot(x_s, yv, lane, w);
        if (lane == 0) upart[0][w] = a0;
    }

    for (int k = 0; k < NCHUNK; k++) {
        if (k + 1 < NCHUNK) {
            if (k + 4 < NCHUNK) {
                asm volatile("cp.async.wait_group 3;\n" ::: "memory");  // chunk k+1 landed
            } else {
                asm volatile("cp.async.wait_group 0;\n" ::: "memory");  // drain tail
            }
        }
        __syncthreads();  // chunk k+1 + upart[k&1] visible; slot (k+5)%6 free

        if (k + 5 < NCHUNK)
            prefetch_chunk(x_s, (k + 5) % NBUF, Xb + (size_t)(k + 5) * CHUNK_FLOATS, t);

        if (k + 1 < NCHUNK) {
            float a0 = p1_dot(x_s + ((k + 1) % NBUF) * CHUNK_FLOATS, yv, lane, w);
            if (lane == 0) upart[(k + 1) & 1][w] = a0;
        }

        // phase2(chunk k): acc += row_k * u_k
        {
            const float* up = upart[k & 1];
            float u0 = invn * (((up[0] + up[1]) + (up[2] + up[3]))
                             + ((up[4] + up[5]) + (up[6] + up[7])));
            const float4* x0 = (const float4*)(x_s + (k % NBUF) * CHUNK_FLOATS) + t;
#pragma unroll
            for (int j = 0; j < 4; j++) {
                float4 r0 = x0[256 * j];
                acc4[j].x += r0.x * u0;
                acc4[j].y += r0.y * u0;
                acc4[j].z += r0.z * u0;
                acc4[j].w += r0.w * u0;
            }
        }
    }

    // epilogue: write w partials + alpha partial
    float d = 0.f;
    float4* wp = (float4*)(g_wpart + (size_t)b * NCOLS);
#pragma unroll
    for (int j = 0; j < 4; j++) {
        wp[t + 256 * j] = acc4[j];
        float4 vv = __ldg(&yv[t + 256 * j]);
        d += acc4[j].x * vv.x + acc4[j].y * vv.y + acc4[j].z * vv.z + acc4[j].w * vv.w;
    }
    red[t] = d;
    __syncthreads();
    for (int s = 128; s > 0; s >>= 1) {
        if (t < s) red[t] += red[t + s];
        __syncthreads();
    }
    if (t == 0) g_dot[b] = red[0] * invn;
}

// ---------------- reduce: w, alpha, orthogonalize, next y + norm partials ----------------
__global__ void __launch_bounds__(1024) k_reduce(int it) {
    __shared__ float sa[1024];
    __shared__ float4 sp[32][32];   // [slice][col-group] 16KB
    int t = threadIdx.x;
    int lane = t & 31;
    int slice = t >> 5;                       // 0..31, 8 b-values each
    int cg = blockIdx.x * 32 + lane;          // float4 column-group, 0..1023

    // wpart partial-sum loads first (overlap with alpha reduce)
    float4 wsum = make_float4(0.f, 0.f, 0.f, 0.f);
    {
        const float4* wp = (const float4*)g_wpart + cg;
#pragma unroll
        for (int i = 0; i < 8; i++) {
            float4 v = wp[(size_t)(slice * 8 + i) * (NCOLS / 4)];
            wsum.x += v.x; wsum.y += v.y; wsum.z += v.z; wsum.w += v.w;
        }
    }

    // alpha = fixed-order tree over 256 dot partials
    sa[t] = (t < NBLK) ? g_dot[t] : 0.f;
    __syncthreads();
    for (int s = 512; s > 0; s >>= 1) {
        if (t < s) sa[t] += sa[t + s];
        __syncthreads();
    }
    float alpha = sa[0];

    // combine 32 slices per column-group (fixed-order tree)
    sp[slice][lane] = wsum;
    __syncthreads();
    for (int s = 16; s > 0; s >>= 1) {
        if (slice < s) {
            float4 o = sp[slice + s][lane];
            sp[slice][lane].x += o.x; sp[slice][lane].y += o.y;
            sp[slice][lane].z += o.z; sp[slice][lane].w += o.w;
        }
        __syncthreads();
    }

    if (slice == 0) {
        float ssum = 0.f;
#pragma unroll
        for (int p = 0; p < RBLK; p++) ssum += g_ss[it * RBLK + p];
        float n = sqrtf(ssum);
        float invn = 1.0f / n;
        float bco = 0.f, invnp = 0.f;
        if (it > 0) {
            float spv = 0.f;
#pragma unroll
            for (int p = 0; p < RBLK; p++) spv += g_ss[(it - 1) * RBLK + p];
            invnp = 1.0f / sqrtf(spv);
            bco = n;
        }
        float ca = alpha * invn, cb = bco * invnp;

        float4 wv = sp[0][lane];
        const float4* ycur = (const float4*)(g_y + (it % 3) * NCOLS);
        const float4* yprv = (const float4*)(g_y + ((it + 2) % 3) * NCOLS);
        float4* ynxt = (float4*)(g_y + ((it + 1) % 3) * NCOLS);
        float4 vc = ycur[cg], vp4 = yprv[cg];
        float4 yt;
        yt.x = wv.x - ca * vc.x - cb * vp4.x;
        yt.y = wv.y - ca * vc.y - cb * vp4.y;
        yt.z = wv.z - ca * vc.z - cb * vp4.z;
        yt.w = wv.w - ca * vc.w - cb * vp4.w;
        ynxt[cg] = yt;

        float nrm = yt.x * yt.x + yt.y * yt.y + yt.z * yt.z + yt.w * yt.w;
#pragma unroll
        for (int o = 16; o > 0; o >>= 1) nrm += __shfl_down_sync(0xffffffffu, nrm, o);
        if (lane == 0) g_ss[(it + 1) * RBLK + blockIdx.x] = nrm;
        if (blockIdx.x == 0 && t == 0) g_alpha[it] = alpha;
    }
}

// ---------------- lambda_max of tridiagonal: warp-parallel Sturm bisection (fp64) ----------------
__global__ void k_tridiag(float* out) {
    __shared__ double a[T_ITERS], b2[T_ITERS];
    int lane = threadIdx.x;
    for (int i = lane; i < T_ITERS; i += 32) {
        a[i] = (double)g_alpha[i];
        double s = 0.0;
        if (i > 0) {
            for (int p = 0; p < RBLK; p++) s += (double)g_ss[i * RBLK + p];
        }
        b2[i] = s;  // beta_i^2 couples rows i-1, i
    }
    __syncwarp();

    double lo = 1e300, hi = -1e300;
    for (int i = lane; i < T_ITERS; i += 32) {
        double r = sqrt(b2[i]) + ((i + 1 < T_ITERS) ? sqrt(b2[i + 1]) : 0.0);
        lo = fmin(lo, a[i] - r);
        hi = fmax(hi, a[i] + r);
    }
#pragma unroll
    for (int o = 16; o > 0; o >>= 1) {
        lo = fmin(lo, __shfl_xor_sync(0xffffffffu, lo, o));
        hi = fmax(hi, __shfl_xor_sync(0xffffffffu, hi, o));
    }
    lo -= 1.0; hi += 1.0;

    for (int round = 0; round < 6; round++) {
        double wdt = (hi - lo) / 33.0;
        double x = lo + wdt * (double)(lane + 1);
        int cnt = 0;
        double d = a[0] - x;
        if (d == 0.0) d = -1e-300;
        if (d < 0.0) cnt++;
        for (int i = 1; i < T_ITERS; i++) {
            d = a[i] - x - b2[i] / d;
            if (d == 0.0) d = -1e-300;
            if (d < 0.0) cnt++;
        }
        unsigned m = __ballot_sync(0xffffffffu, cnt >= T_ITERS);
        if (m) {
            int f = __ffs(m) - 1;
            hi = lo + wdt * (double)(f + 1);
            lo = lo + wdt * (double)f;
        } else {
            lo = lo + wdt * 32.0;
        }
    }
    if (lane == 0) out[0] = (float)(0.5 * (lo + hi));  // sigma_1^2
}

// ---------------- launch ----------------
extern "C" void kernel_launch(void* const* d_in, const int* in_sizes, int n_in,
                              void* d_out, int out_size) {
    const float* X = (const float*)d_in[0];
    float* out = (float*)d_out;

    cudaFuncSetAttribute(k_matvec, cudaFuncAttributeMaxDynamicSharedMemorySize, SMEM_BYTES);

    k_init<<<1, 1024>>>();
    for (int it = 0; it < T_ITERS; it++) {
        k_matvec<<<NBLK, 256, SMEM_BYTES>>>(X, it);
        k_reduce<<<RBLK, 1024>>>(it);
    }
    k_tridiag<<<1, 32>>>(out);
}

// round 5
// speedup vs baseline: 11.3602x; 1.2309x over previous
#include <cuda_runtime.h>
#include <cuda_bf16.h>
#include <math.h>

#define MROWS 8192
#define NCOLS 4096
#define T_ITERS 64
#define NBLK 256               // matvec blocks
#define RPB 32                 // rows per matvec block
#define NCHUNK 32              // 1 row per chunk
#define CHUNK_BYTES (NCOLS * 2)        // 8KB (bf16 row)
#define CHUNK_U4 (CHUNK_BYTES / 16)    // 512 uint4
#define NBUF 6
#define RBLK 32                // reduce blocks
#define SMEM_BYTES (NBUF * CHUNK_BYTES)  // 48KB

// ---------------- device scratch ----------------
__device__ __nv_bfloat16 g_Xb[(size_t)MROWS * NCOLS];  // 67MB bf16 copy of X
__device__ float g_y[3 * NCOLS];
__device__ float g_wpart[NBLK * NCOLS];
__device__ float g_dot[NBLK];
__device__ float g_ss[(T_ITERS + 1) * RBLK];
__device__ float g_alpha[T_ITERS];

// ---------------- one-time fp32 -> bf16 conversion ----------------
__global__ void __launch_bounds__(256) k_tobf16(const float* __restrict__ X) {
    const float4* X4 = (const float4*)X;
    uint2* out = (uint2*)g_Xb;
    size_t base = (size_t)blockIdx.x * 1024 + threadIdx.x;
#pragma unroll
    for (int i = 0; i < 4; i++) {
        size_t idx = base + (size_t)i * 256;
        float4 v = X4[idx];
        __nv_bfloat162 h0 = __float22bfloat162_rn(make_float2(v.x, v.y));
        __nv_bfloat162 h1 = __float22bfloat162_rn(make_float2(v.z, v.w));
        uint2 o;
        o.x = *(unsigned*)&h0;
        o.y = *(unsigned*)&h1;
        out[idx] = o;
    }
}

// ---------------- init: deterministic pseudo-random unit vector ----------------
__global__ void k_init() {
    __shared__ float red[1024];
    int t = threadIdx.x;
    float vals[4];
    float ss = 0.f;
#pragma unroll
    for (int i = 0; i < 4; i++) {
        int j = t + i * 1024;
        unsigned h = (unsigned)j * 2654435761u;
        h ^= h >> 16; h *= 2246822519u; h ^= h >> 13;
        float x = (float)(h & 0xFFFFFF) * (1.0f / 16777216.0f) - 0.5f;
        vals[i] = x;
        ss += x * x;
    }
    red[t] = ss;
    __syncthreads();
    for (int s = 512; s > 0; s >>= 1) {
        if (t < s) red[t] += red[t + s];
        __syncthreads();
    }
    float inv = rsqrtf(red[0]);
#pragma unroll
    for (int i = 0; i < 4; i++) {
        int j = t + i * 1024;
        g_y[j] = vals[i] * inv;
        g_y[2 * NCOLS + j] = 0.f;
    }
    if (t == 0) {
#pragma unroll
        for (int p = 0; p < RBLK; p++) g_ss[p] = (p == 0) ? 1.f : 0.f;
    }
}

// ---------------- fused matvec on bf16 X ----------------
__device__ __forceinline__ void prefetch_chunk(void* x_s, int slot, const uint4* src, int t) {
    unsigned base = (unsigned)__cvta_generic_to_shared((char*)x_s + slot * CHUNK_BYTES) + t * 16;
    asm volatile("cp.async.cg.shared.global [%0], [%1], 16;\n"
                 :: "r"(base), "l"(src + t) : "memory");
    asm volatile("cp.async.cg.shared.global [%0], [%1], 16;\n"
                 :: "r"(base + 4096), "l"(src + 256 + t) : "memory");
    asm volatile("cp.async.commit_group;\n" ::: "memory");
}

__device__ __forceinline__ float dot8(uint4 xb, float4 a, float4 b) {
    float2 f0 = __bfloat1622float2(*(__nv_bfloat162*)&xb.x);
    float2 f1 = __bfloat1622float2(*(__nv_bfloat162*)&xb.y);
    float2 f2 = __bfloat1622float2(*(__nv_bfloat162*)&xb.z);
    float2 f3 = __bfloat1622float2(*(__nv_bfloat162*)&xb.w);
    return f0.x * a.x + f0.y * a.y + f1.x * a.z + f1.y * a.w
         + f2.x * b.x + f2.y * b.y + f3.x * b.z + f3.y * b.w;
}

extern __shared__ uint4 x_s[];

// phase1: warp-partial dot of bf16 chunk row with v (fp32)
__device__ __forceinline__ float p1_dot(const uint4* xs, const float4* yv, int lane, int w) {
    float a0 = 0.f;
#pragma unroll
    for (int i = 0; i < 2; i++) {
        int id = w * 64 + 32 * i + lane;
        uint4 xb = xs[id];
        float4 ya = __ldg(&yv[2 * id]);
        float4 yb = __ldg(&yv[2 * id + 1]);
        a0 += dot8(xb, ya, yb);
    }
#pragma unroll
    for (int o = 16; o > 0; o >>= 1) a0 += __shfl_down_sync(0xffffffffu, a0, o);
    return a0;
}

__global__ void __launch_bounds__(256, 3) k_matvec(int it) {
    __shared__ float upart[2][8];
    __shared__ float red[256];
    int t = threadIdx.x, b = blockIdx.x;
    int lane = t & 31, w = t >> 5;

    float ssum = 0.f;
#pragma unroll
    for (int p = 0; p < RBLK; p++) ssum += g_ss[it * RBLK + p];
    float invn = 1.0f / sqrtf(ssum);

    const float4* yv = (const float4*)(g_y + (it % 3) * NCOLS);
    const uint4* Xb = (const uint4*)(g_Xb + (size_t)b * RPB * NCOLS);

    float acc[16];
#pragma unroll
    for (int i = 0; i < 16; i++) acc[i] = 0.f;

    // prologue: 5 chunk loads in flight
#pragma unroll
    for (int c = 0; c < 5; c++) prefetch_chunk(x_s, c, Xb + (size_t)c * CHUNK_U4, t);
    asm volatile("cp.async.wait_group 4;\n" ::: "memory");
    __syncthreads();
    {
        float a0 = p1_dot(x_s, yv, lane, w);
        if (lane == 0) upart[0][w] = a0;
    }

    for (int k = 0; k < NCHUNK; k++) {
        if (k + 1 < NCHUNK) {
            if (k + 4 < NCHUNK) {
                asm volatile("cp.async.wait_group 3;\n" ::: "memory");
            } else {
                asm volatile("cp.async.wait_group 0;\n" ::: "memory");
            }
        }
        __syncthreads();

        if (k + 5 < NCHUNK)
            prefetch_chunk(x_s, (k + 5) % NBUF, Xb + (size_t)(k + 5) * CHUNK_U4, t);

        if (k + 1 < NCHUNK) {
            float a0 = p1_dot(x_s + ((k + 1) % NBUF) * CHUNK_U4, yv, lane, w);
            if (lane == 0) upart[(k + 1) & 1][w] = a0;
        }

        // phase2(chunk k): acc += row_k * u_k
        {
            const float* up = upart[k & 1];
            float u0 = invn * (((up[0] + up[1]) + (up[2] + up[3]))
                             + ((up[4] + up[5]) + (up[6] + up[7])));
            const uint4* x0 = x_s + (k % NBUF) * CHUNK_U4 + t;
#pragma unroll
            for (int j = 0; j < 2; j++) {
                uint4 xb = x0[256 * j];
                float2 f0 = __bfloat1622float2(*(__nv_bfloat162*)&xb.x);
                float2 f1 = __bfloat1622float2(*(__nv_bfloat162*)&xb.y);
                float2 f2 = __bfloat1622float2(*(__nv_bfloat162*)&xb.z);
                float2 f3 = __bfloat1622float2(*(__nv_bfloat162*)&xb.w);
                acc[8 * j + 0] += f0.x * u0; acc[8 * j + 1] += f0.y * u0;
                acc[8 * j + 2] += f1.x * u0; acc[8 * j + 3] += f1.y * u0;
                acc[8 * j + 4] += f2.x * u0; acc[8 * j + 5] += f2.y * u0;
                acc[8 * j + 6] += f3.x * u0; acc[8 * j + 7] += f3.y * u0;
            }
        }
    }

    // epilogue: write w partials (fp32) + alpha partial
    float d = 0.f;
    float4* wp = (float4*)(g_wpart + (size_t)b * NCOLS);
#pragma unroll
    for (int j = 0; j < 2; j++) {
#pragma unroll
        for (int h = 0; h < 2; h++) {
            int fi = j * 512 + 2 * t + h;
            float4 av = make_float4(acc[8 * j + 4 * h + 0], acc[8 * j + 4 * h + 1],
                                    acc[8 * j + 4 * h + 2], acc[8 * j + 4 * h + 3]);
            wp[fi] = av;
            float4 vv = __ldg(&yv[fi]);
            d += av.x * vv.x + av.y * vv.y + av.z * vv.z + av.w * vv.w;
        }
    }
    red[t] = d;
    __syncthreads();
    for (int s = 128; s > 0; s >>= 1) {
        if (t < s) red[t] += red[t + s];
        __syncthreads();
    }
    if (t == 0) g_dot[b] = red[0] * invn;
}

// ---------------- reduce: w, alpha, orthogonalize, next y + norm partials ----------------
__global__ void __launch_bounds__(1024) k_reduce(int it) {
    __shared__ float sa[1024];
    __shared__ float4 sp[32][32];
    int t = threadIdx.x;
    int lane = t & 31;
    int slice = t >> 5;
    int cg = blockIdx.x * 32 + lane;

    float4 wsum = make_float4(0.f, 0.f, 0.f, 0.f);
    {
        const float4* wp = (const float4*)g_wpart + cg;
#pragma unroll
        for (int i = 0; i < 8; i++) {
            float4 v = wp[(size_t)(slice * 8 + i) * (NCOLS / 4)];
            wsum.x += v.x; wsum.y += v.y; wsum.z += v.z; wsum.w += v.w;
        }
    }

    sa[t] = (t < NBLK) ? g_dot[t] : 0.f;
    __syncthreads();
    for (int s = 512; s > 0; s >>= 1) {
        if (t < s) sa[t] += sa[t + s];
        __syncthreads();
    }
    float alpha = sa[0];

    sp[slice][lane] = wsum;
    __syncthreads();
    for (int s = 16; s > 0; s >>= 1) {
        if (slice < s) {
            float4 o = sp[slice + s][lane];
            sp[slice][lane].x += o.x; sp[slice][lane].y += o.y;
            sp[slice][lane].z += o.z; sp[slice][lane].w += o.w;
        }
        __syncthreads();
    }

    if (slice == 0) {
        float ssum = 0.f;
#pragma unroll
        for (int p = 0; p < RBLK; p++) ssum += g_ss[it * RBLK + p];
        float n = sqrtf(ssum);
        float invn = 1.0f / n;
        float bco = 0.f, invnp = 0.f;
        if (it > 0) {
            float spv = 0.f;
#pragma unroll
            for (int p = 0; p < RBLK; p++) spv += g_ss[(it - 1) * RBLK + p];
            invnp = 1.0f / sqrtf(spv);
            bco = n;
        }
        float ca = alpha * invn, cb = bco * invnp;

        float4 wv = sp[0][lane];
        const float4* ycur = (const float4*)(g_y + (it % 3) * NCOLS);
        const float4* yprv = (const float4*)(g_y + ((it + 2) % 3) * NCOLS);
        float4* ynxt = (float4*)(g_y + ((it + 1) % 3) * NCOLS);
        float4 vc = ycur[cg], vp4 = yprv[cg];
        float4 yt;
        yt.x = wv.x - ca * vc.x - cb * vp4.x;
        yt.y = wv.y - ca * vc.y - cb * vp4.y;
        yt.z = wv.z - ca * vc.z - cb * vp4.z;
        yt.w = wv.w - ca * vc.w - cb * vp4.w;
        ynxt[cg] = yt;

        float nrm = yt.x * yt.x + yt.y * yt.y + yt.z * yt.z + yt.w * yt.w;
#pragma unroll
        for (int o = 16; o > 0; o >>= 1) nrm += __shfl_down_sync(0xffffffffu, nrm, o);
        if (lane == 0) g_ss[(it + 1) * RBLK + blockIdx.x] = nrm;
        if (blockIdx.x == 0 && t == 0) g_alpha[it] = alpha;
    }
}

// ---------------- lambda_max of tridiagonal: warp-parallel Sturm bisection (fp64) ----------------
__global__ void k_tridiag(float* out) {
    __shared__ double a[T_ITERS], b2[T_ITERS];
    int lane = threadIdx.x;
    for (int i = lane; i < T_ITERS; i += 32) {
        a[i] = (double)g_alpha[i];
        double s = 0.0;
        if (i > 0) {
            for (int p = 0; p < RBLK; p++) s += (double)g_ss[i * RBLK + p];
        }
        b2[i] = s;
    }
    __syncwarp();

    double lo = 1e300, hi = -1e300;
    for (int i = lane; i < T_ITERS; i += 32) {
        double r = sqrt(b2[i]) + ((i + 1 < T_ITERS) ? sqrt(b2[i + 1]) : 0.0);
        lo = fmin(lo, a[i] - r);
        hi = fmax(hi, a[i] + r);
    }
#pragma unroll
    for (int o = 16; o > 0; o >>= 1) {
        lo = fmin(lo, __shfl_xor_sync(0xffffffffu, lo, o));
        hi = fmax(hi, __shfl_xor_sync(0xffffffffu, hi, o));
    }
    lo -= 1.0; hi += 1.0;

    for (int round = 0; round < 6; round++) {
        double wdt = (hi - lo) / 33.0;
        double x = lo + wdt * (double)(lane + 1);
        int cnt = 0;
        double d = a[0] - x;
        if (d == 0.0) d = -1e-300;
        if (d < 0.0) cnt++;
        for (int i = 1; i < T_ITERS; i++) {
            d = a[i] - x - b2[i] / d;
            if (d == 0.0) d = -1e-300;
            if (d < 0.0) cnt++;
        }
        unsigned m = __ballot_sync(0xffffffffu, cnt >= T_ITERS);
        if (m) {
            int f = __ffs(m) - 1;
            hi = lo + wdt * (double)(f + 1);
            lo = lo + wdt * (double)f;
        } else {
            lo = lo + wdt * 32.0;
        }
    }
    if (lane == 0) out[0] = (float)(0.5 * (lo + hi));
}

// ---------------- launch ----------------
extern "C" void kernel_launch(void* const* d_in, const int* in_sizes, int n_in,
                              void* d_out, int out_size) {
    const float* X = (const float*)d_in[0];
    float* out = (float*)d_out;

    cudaFuncSetAttribute(k_matvec, cudaFuncAttributeMaxDynamicSharedMemorySize, SMEM_BYTES);

    k_tobf16<<<8192, 256>>>(X);
    k_init<<<1, 1024>>>();
    for (int it = 0; it < T_ITERS; it++) {
        k_matvec<<<NBLK, 256, SMEM_BYTES>>>(it);
        k_reduce<<<RBLK, 1024>>>(it);
    }
    k_tridiag<<<1, 32>>>(out);
}

// round 6
// speedup vs baseline: 15.2516x; 1.3425x over previous
#include <cuda_runtime.h>
#include <cuda_bf16.h>
#include <math.h>

#define MROWS 8192
#define NCOLS 4096
#define T_ITERS 48
#define NBLK 256               // matvec blocks
#define RPB 32                 // rows per matvec block
#define NCHUNK 32              // 1 row per chunk
#define CHUNK_BYTES (NCOLS * 2)        // 8KB (bf16 row)
#define CHUNK_U4 (CHUNK_BYTES / 16)    // 512 uint4
#define NBUF 6
#define RBLK 128               // reduce blocks (= norm partials per iter)
#define SMEM_BYTES (NBUF * CHUNK_BYTES)  // 48KB

// ---------------- device scratch ----------------
__device__ __nv_bfloat16 g_Xb[(size_t)MROWS * NCOLS];  // 67MB bf16 copy of X
__device__ float g_y[3 * NCOLS];
__device__ float g_wpart[NBLK * NCOLS];
__device__ float g_dot[NBLK];
__device__ float g_ss[(T_ITERS + 1) * RBLK];
__device__ float g_alpha[T_ITERS];

// ---------------- one-time fp32 -> bf16 conversion ----------------
__global__ void __launch_bounds__(256) k_tobf16(const float* __restrict__ X) {
    const float4* X4 = (const float4*)X;
    uint2* out = (uint2*)g_Xb;
    size_t base = (size_t)blockIdx.x * 1024 + threadIdx.x;
#pragma unroll
    for (int i = 0; i < 4; i++) {
        size_t idx = base + (size_t)i * 256;
        float4 v = X4[idx];
        __nv_bfloat162 h0 = __float22bfloat162_rn(make_float2(v.x, v.y));
        __nv_bfloat162 h1 = __float22bfloat162_rn(make_float2(v.z, v.w));
        uint2 o;
        o.x = *(unsigned*)&h0;
        o.y = *(unsigned*)&h1;
        out[idx] = o;
    }
}

// ---------------- init: deterministic pseudo-random unit vector ----------------
__global__ void k_init() {
    __shared__ float red[1024];
    int t = threadIdx.x;
    float vals[4];
    float ss = 0.f;
#pragma unroll
    for (int i = 0; i < 4; i++) {
        int j = t + i * 1024;
        unsigned h = (unsigned)j * 2654435761u;
        h ^= h >> 16; h *= 2246822519u; h ^= h >> 13;
        float x = (float)(h & 0xFFFFFF) * (1.0f / 16777216.0f) - 0.5f;
        vals[i] = x;
        ss += x * x;
    }
    red[t] = ss;
    __syncthreads();
    for (int s = 512; s > 0; s >>= 1) {
        if (t < s) red[t] += red[t + s];
        __syncthreads();
    }
    float inv = rsqrtf(red[0]);
#pragma unroll
    for (int i = 0; i < 4; i++) {
        int j = t + i * 1024;
        g_y[j] = vals[i] * inv;
        g_y[2 * NCOLS + j] = 0.f;
    }
    if (t == 0) {
        for (int p = 0; p < RBLK; p++) g_ss[p] = (p == 0) ? 1.f : 0.f;
    }
}

// ---------------- fused matvec on bf16 X ----------------
__device__ __forceinline__ void prefetch_chunk(void* x_s, int slot, const uint4* src, int t) {
    unsigned base = (unsigned)__cvta_generic_to_shared((char*)x_s + slot * CHUNK_BYTES) + t * 16;
    asm volatile("cp.async.cg.shared.global [%0], [%1], 16;\n"
                 :: "r"(base), "l"(src + t) : "memory");
    asm volatile("cp.async.cg.shared.global [%0], [%1], 16;\n"
                 :: "r"(base + 4096), "l"(src + 256 + t) : "memory");
    asm volatile("cp.async.commit_group;\n" ::: "memory");
}

__device__ __forceinline__ float dot8(uint4 xb, float4 a, float4 b) {
    float2 f0 = __bfloat1622float2(*(__nv_bfloat162*)&xb.x);
    float2 f1 = __bfloat1622float2(*(__nv_bfloat162*)&xb.y);
    float2 f2 = __bfloat1622float2(*(__nv_bfloat162*)&xb.z);
    float2 f3 = __bfloat1622float2(*(__nv_bfloat162*)&xb.w);
    return f0.x * a.x + f0.y * a.y + f1.x * a.z + f1.y * a.w
         + f2.x * b.x + f2.y * b.y + f3.x * b.z + f3.y * b.w;
}

extern __shared__ uint4 x_s[];

// phase1: warp-partial dot of bf16 chunk row with v (fp32)
__device__ __forceinline__ float p1_dot(const uint4* xs, const float4* yv, int lane, int w) {
    float a0 = 0.f;
#pragma unroll
    for (int i = 0; i < 2; i++) {
        int id = w * 64 + 32 * i + lane;
        uint4 xb = xs[id];
        float4 ya = __ldg(&yv[2 * id]);
        float4 yb = __ldg(&yv[2 * id + 1]);
        a0 += dot8(xb, ya, yb);
    }
#pragma unroll
    for (int o = 16; o > 0; o >>= 1) a0 += __shfl_down_sync(0xffffffffu, a0, o);
    return a0;
}

__global__ void __launch_bounds__(256, 3) k_matvec(int it) {
    __shared__ float upart[2][8];
    __shared__ float red[256];
    __shared__ float s_invn;
    int t = threadIdx.x, b = blockIdx.x;
    int lane = t & 31, w = t >> 5;

    const float4* yv = (const float4*)(g_y + (it % 3) * NCOLS);
    const uint4* Xb = (const uint4*)(g_Xb + (size_t)b * RPB * NCOLS);

    float acc[16];
#pragma unroll
    for (int i = 0; i < 16; i++) acc[i] = 0.f;

    // prologue: 5 chunk loads in flight
#pragma unroll
    for (int c = 0; c < 5; c++) prefetch_chunk(x_s, c, Xb + (size_t)c * CHUNK_U4, t);

    // invn = 1/||y|| from 128 partials (warp 0, overlapped with prefetch latency)
    if (w == 0) {
        const float* sb = g_ss + it * RBLK;
        float s = sb[lane] + sb[lane + 32] + sb[lane + 64] + sb[lane + 96];
#pragma unroll
        for (int o = 16; o > 0; o >>= 1) s += __shfl_down_sync(0xffffffffu, s, o);
        if (lane == 0) s_invn = rsqrtf(s);
    }

    asm volatile("cp.async.wait_group 4;\n" ::: "memory");
    __syncthreads();
    float invn = s_invn;
    {
        float a0 = p1_dot(x_s, yv, lane, w);
        if (lane == 0) upart[0][w] = a0;
    }

    for (int k = 0; k < NCHUNK; k++) {
        if (k + 1 < NCHUNK) {
            if (k + 4 < NCHUNK) {
                asm volatile("cp.async.wait_group 3;\n" ::: "memory");
            } else {
                asm volatile("cp.async.wait_group 0;\n" ::: "memory");
            }
        }
        __syncthreads();

        if (k + 5 < NCHUNK)
            prefetch_chunk(x_s, (k + 5) % NBUF, Xb + (size_t)(k + 5) * CHUNK_U4, t);

        if (k + 1 < NCHUNK) {
            float a0 = p1_dot(x_s + ((k + 1) % NBUF) * CHUNK_U4, yv, lane, w);
            if (lane == 0) upart[(k + 1) & 1][w] = a0;
        }

        // phase2(chunk k): acc += row_k * u_k
        {
            const float* up = upart[k & 1];
            float u0 = invn * (((up[0] + up[1]) + (up[2] + up[3]))
                             + ((up[4] + up[5]) + (up[6] + up[7])));
            const uint4* x0 = x_s + (k % NBUF) * CHUNK_U4 + t;
#pragma unroll
            for (int j = 0; j < 2; j++) {
                uint4 xb = x0[256 * j];
                float2 f0 = __bfloat1622float2(*(__nv_bfloat162*)&xb.x);
                float2 f1 = __bfloat1622float2(*(__nv_bfloat162*)&xb.y);
                float2 f2 = __bfloat1622float2(*(__nv_bfloat162*)&xb.z);
                float2 f3 = __bfloat1622float2(*(__nv_bfloat162*)&xb.w);
                acc[8 * j + 0] += f0.x * u0; acc[8 * j + 1] += f0.y * u0;
                acc[8 * j + 2] += f1.x * u0; acc[8 * j + 3] += f1.y * u0;
                acc[8 * j + 4] += f2.x * u0; acc[8 * j + 5] += f2.y * u0;
                acc[8 * j + 6] += f3.x * u0; acc[8 * j + 7] += f3.y * u0;
            }
        }
    }

    // epilogue: write w partials (fp32) + alpha partial
    float d = 0.f;
    float4* wp = (float4*)(g_wpart + (size_t)b * NCOLS);
#pragma unroll
    for (int j = 0; j < 2; j++) {
#pragma unroll
        for (int h = 0; h < 2; h++) {
            int fi = j * 512 + 2 * t + h;
            float4 av = make_float4(acc[8 * j + 4 * h + 0], acc[8 * j + 4 * h + 1],
                                    acc[8 * j + 4 * h + 2], acc[8 * j + 4 * h + 3]);
            wp[fi] = av;
            float4 vv = __ldg(&yv[fi]);
            d += av.x * vv.x + av.y * vv.y + av.z * vv.z + av.w * vv.w;
        }
    }
    red[t] = d;
    __syncthreads();
    for (int s = 128; s > 0; s >>= 1) {
        if (t < s) red[t] += red[t + s];
        __syncthreads();
    }
    if (t == 0) g_dot[b] = red[0] * invn;
}

// ---------------- reduce: 128 blocks x 256 threads, 8 col-groups (32 cols) per block ----------------
__global__ void __launch_bounds__(256) k_reduce(int it) {
    __shared__ float4 sp[32][8];     // [slice][col-group-local]
    __shared__ float sred[16];       // 8 alpha warp-partials + 8 norm warp-partials
    __shared__ float s_ca, s_cb;
    int t = threadIdx.x;
    int lane = t & 31, w = t >> 5;
    int cgl = t & 7;                 // col-group local 0..7
    int slice = t >> 3;              // 0..31
    int cg = blockIdx.x * 8 + cgl;   // global float4 col-group 0..1023

    // wpart partial sums: 8 partials per thread (coalesced: 8 consecutive cgl per slice row)
    float4 wsum = make_float4(0.f, 0.f, 0.f, 0.f);
    {
        const float4* wp = (const float4*)g_wpart + cg;
#pragma unroll
        for (int i = 0; i < 8; i++) {
            float4 v = wp[(size_t)(slice * 8 + i) * (NCOLS / 4)];
            wsum.x += v.x; wsum.y += v.y; wsum.z += v.z; wsum.w += v.w;
        }
    }
    sp[slice][cgl] = wsum;

    // alpha warp-partials over 256 dot entries
    {
        float dv = g_dot[t];
#pragma unroll
        for (int o = 16; o > 0; o >>= 1) dv += __shfl_down_sync(0xffffffffu, dv, o);
        if (lane == 0) sred[w] = dv;
    }
    // norm partials: warps 0-3 current, warps 4-7 previous
    {
        float nv;
        if (w < 4) nv = g_ss[it * RBLK + t];
        else nv = (it > 0) ? g_ss[(it - 1) * RBLK + (t - 128)] : 0.f;
#pragma unroll
        for (int o = 16; o > 0; o >>= 1) nv += __shfl_down_sync(0xffffffffu, nv, o);
        if (lane == 0) sred[8 + w] = nv;
    }
    __syncthreads();

    // slice tree (fixed order)
    for (int s = 16; s > 0; s >>= 1) {
        if (slice < s) {
            float4 o = sp[slice + s][cgl];
            sp[slice][cgl].x += o.x; sp[slice][cgl].y += o.y;
            sp[slice][cgl].z += o.z; sp[slice][cgl].w += o.w;
        }
        __syncthreads();
    }

    if (t == 0) {
        float alpha = ((sred[0] + sred[1]) + (sred[2] + sred[3]))
                    + ((sred[4] + sred[5]) + (sred[6] + sred[7]));
        float ssum  = (sred[8] + sred[9]) + (sred[10] + sred[11]);
        float ssp   = (sred[12] + sred[13]) + (sred[14] + sred[15]);
        float n = sqrtf(ssum);
        float invn = 1.0f / n;
        s_ca = alpha * invn;
        s_cb = (it > 0) ? n * rsqrtf(ssp) : 0.f;
        if (blockIdx.x == 0) g_alpha[it] = alpha;
    }
    __syncthreads();

    if (slice == 0) {   // 8 threads, one col-group each
        float ca = s_ca, cb = s_cb;
        float4 wv = sp[0][cgl];
        const float4* ycur = (const float4*)(g_y + (it % 3) * NCOLS);
        const float4* yprv = (const float4*)(g_y + ((it + 2) % 3) * NCOLS);
        float4* ynxt = (float4*)(g_y + ((it + 1) % 3) * NCOLS);
        float4 vc = ycur[cg], vp4 = yprv[cg];
        float4 yt;
        yt.x = wv.x - ca * vc.x - cb * vp4.x;
        yt.y = wv.y - ca * vc.y - cb * vp4.y;
        yt.z = wv.z - ca * vc.z - cb * vp4.z;
        yt.w = wv.w - ca * vc.w - cb * vp4.w;
        ynxt[cg] = yt;
        sred[cgl] = yt.x * yt.x + yt.y * yt.y + yt.z * yt.z + yt.w * yt.w;
    }
    __syncthreads();
    if (t == 0) {
        float s = ((sred[0] + sred[1]) + (sred[2] + sred[3]))
                + ((sred[4] + sred[5]) + (sred[6] + sred[7]));
        g_ss[(it + 1) * RBLK + blockIdx.x] = s;
    }
}

// ---------------- lambda_max of tridiagonal: warp-parallel Sturm bisection (fp64) ----------------
__global__ void k_tridiag(float* out) {
    __shared__ double a[T_ITERS], b2[T_ITERS];
    int lane = threadIdx.x;
    for (int i = lane; i < T_ITERS; i += 32) {
        a[i] = (double)g_alpha[i];
        double s = 0.0;
        if (i > 0) {
            for (int p = 0; p < RBLK; p++) s += (double)g_ss[i * RBLK + p];
        }
        b2[i] = s;
    }
    __syncwarp();

    double lo = 1e300, hi = -1e300;
    for (int i = lane; i < T_ITERS; i += 32) {
        double r = sqrt(b2[i]) + ((i + 1 < T_ITERS) ? sqrt(b2[i + 1]) : 0.0);
        lo = fmin(lo, a[i] - r);
        hi = fmax(hi, a[i] + r);
    }
#pragma unroll
    for (int o = 16; o > 0; o >>= 1) {
        lo = fmin(lo, __shfl_xor_sync(0xffffffffu, lo, o));
        hi = fmax(hi, __shfl_xor_sync(0xffffffffu, hi, o));
    }
    lo -= 1.0; hi += 1.0;

    for (int round = 0; round < 6; round++) {
        double wdt = (hi - lo) / 33.0;
        double x = lo + wdt * (double)(lane + 1);
        int cnt = 0;
        double d = a[0] - x;
        if (d == 0.0) d = -1e-300;
        if (d < 0.0) cnt++;
        for (int i = 1; i < T_ITERS; i++) {
            d = a[i] - x - b2[i] / d;
            if (d == 0.0) d = -1e-300;
            if (d < 0.0) cnt++;
        }
        unsigned m = __ballot_sync(0xffffffffu, cnt >= T_ITERS);
        if (m) {
            int f = __ffs(m) - 1;
            hi = lo + wdt * (double)(f + 1);
            lo = lo + wdt * (double)f;
        } else {
            lo = lo + wdt * 32.0;
        }
    }
    if (lane == 0) out[0] = (float)(0.5 * (lo + hi));
}

// ---------------- launch ----------------
extern "C" void kernel_launch(void* const* d_in, const int* in_sizes, int n_in,
                              void* d_out, int out_size) {
    const float* X = (const float*)d_in[0];
    float* out = (float*)d_out;

    cudaFuncSetAttribute(k_matvec, cudaFuncAttributeMaxDynamicSharedMemorySize, SMEM_BYTES);

    k_tobf16<<<8192, 256>>>(X);
    k_init<<<1, 1024>>>();
    for (int it = 0; it < T_ITERS; it++) {
        k_matvec<<<NBLK, 256, SMEM_BYTES>>>(it);
        k_reduce<<<RBLK, 256>>>(it);
    }
    k_tridiag<<<1, 32>>>(out);
}

// round 9
// speedup vs baseline: 18.4468x; 1.2095x over previous
#include <cuda_runtime.h>
#include <cuda_bf16.h>
#include <math.h>

#define MROWS 8192
#define NCOLS 4096
#define T_ITERS 40
#define NBLK 256               // matvec blocks
#define RPB 32                 // rows per matvec block
#define NCHUNK 32              // 1 row per chunk
#define CHUNK_BYTES (NCOLS * 2)        // 8KB (bf16 row)
#define CHUNK_U4 (CHUNK_BYTES / 16)    // 512 uint4
#define NBUF 6
#define REDB 32                // reducer blocks (last arrivals) = norm partials
#define SMEM_BYTES (NBUF * CHUNK_BYTES)  // 48KB

// ---------------- device scratch ----------------
__device__ __nv_bfloat16 g_Xb[(size_t)MROWS * NCOLS];  // 67MB bf16 copy of X
__device__ float g_y[3 * NCOLS];
__device__ float g_wpart[NBLK * NCOLS];
__device__ float g_dot[NBLK];
__device__ float g_ss[(T_ITERS + 1) * REDB];
__device__ float g_alpha[T_ITERS];
__device__ int   g_ctr[T_ITERS];

// ---------------- one-time fp32 -> bf16 conversion ----------------
__global__ void __launch_bounds__(256) k_tobf16(const float* __restrict__ X) {
    const float4* X4 = (const float4*)X;
    uint2* out = (uint2*)g_Xb;
    size_t base = (size_t)blockIdx.x * 1024 + threadIdx.x;
#pragma unroll
    for (int i = 0; i < 4; i++) {
        size_t idx = base + (size_t)i * 256;
        float4 v = X4[idx];
        __nv_bfloat162 h0 = __float22bfloat162_rn(make_float2(v.x, v.y));
        __nv_bfloat162 h1 = __float22bfloat162_rn(make_float2(v.z, v.w));
        uint2 o;
        o.x = *(unsigned*)&h0;
        o.y = *(unsigned*)&h1;
        out[idx] = o;
    }
}

// ---------------- init: deterministic pseudo-random unit vector ----------------
__global__ void k_init() {
    __shared__ float red[1024];
    int t = threadIdx.x;
    float vals[4];
    float ss = 0.f;
#pragma unroll
    for (int i = 0; i < 4; i++) {
        int j = t + i * 1024;
        unsigned h = (unsigned)j * 2654435761u;
        h ^= h >> 16; h *= 2246822519u; h ^= h >> 13;
        float x = (float)(h & 0xFFFFFF) * (1.0f / 16777216.0f) - 0.5f;
        vals[i] = x;
        ss += x * x;
    }
    red[t] = ss;
    __syncthreads();
    for (int s = 512; s > 0; s >>= 1) {
        if (t < s) red[t] += red[t + s];
        __syncthreads();
    }
    float inv = rsqrtf(red[0]);
#pragma unroll
    for (int i = 0; i < 4; i++) {
        int j = t + i * 1024;
        g_y[j] = vals[i] * inv;
        g_y[2 * NCOLS + j] = 0.f;
    }
    if (t < T_ITERS) g_ctr[t] = 0;
    if (t == 0) {
        for (int p = 0; p < REDB; p++) g_ss[p] = (p == 0) ? 1.f : 0.f;
    }
}

// ---------------- fused matvec + last-arrivals reduce ----------------
__device__ __forceinline__ void prefetch_chunk(void* x_s, int slot, const uint4* src, int t) {
    unsigned base = (unsigned)__cvta_generic_to_shared((char*)x_s + slot * CHUNK_BYTES) + t * 16;
    asm volatile("cp.async.cg.shared.global [%0], [%1], 16;\n"
                 :: "r"(base), "l"(src + t) : "memory");
    asm volatile("cp.async.cg.shared.global [%0], [%1], 16;\n"
                 :: "r"(base + 4096), "l"(src + 256 + t) : "memory");
    asm volatile("cp.async.commit_group;\n" ::: "memory");
}

__device__ __forceinline__ float dot8(uint4 xb, float4 a, float4 b) {
    float2 f0 = __bfloat1622float2(*(__nv_bfloat162*)&xb.x);
    float2 f1 = __bfloat1622float2(*(__nv_bfloat162*)&xb.y);
    float2 f2 = __bfloat1622float2(*(__nv_bfloat162*)&xb.z);
    float2 f3 = __bfloat1622float2(*(__nv_bfloat162*)&xb.w);
    return f0.x * a.x + f0.y * a.y + f1.x * a.z + f1.y * a.w
         + f2.x * b.x + f2.y * b.y + f3.x * b.z + f3.y * b.w;
}

extern __shared__ uint4 x_s[];

__device__ __forceinline__ float p1_dot(const uint4* xs, const float4* yv, int lane, int w) {
    float a0 = 0.f;
#pragma unroll
    for (int i = 0; i < 2; i++) {
        int id = w * 64 + 32 * i + lane;
        uint4 xb = xs[id];
        float4 ya = __ldg(&yv[2 * id]);
        float4 yb = __ldg(&yv[2 * id + 1]);
        a0 += dot8(xb, ya, yb);
    }
#pragma unroll
    for (int o = 16; o > 0; o >>= 1) a0 += __shfl_down_sync(0xffffffffu, a0, o);
    return a0;
}

__global__ void __launch_bounds__(256, 3) k_matvec(int it) {
    __shared__ float upart[2][8];
    __shared__ float red[256];
    __shared__ float s_invn;
    __shared__ int s_ticket;
    __shared__ float4 sp[8][32];     // reducer slice tree
    __shared__ float s_scal[4];      // alpha, ssum(cur), ssum(prev)
    int t = threadIdx.x, b = blockIdx.x;
    int lane = t & 31, w = t >> 5;

    const float4* yv = (const float4*)(g_y + (it % 3) * NCOLS);
    const uint4* Xb = (const uint4*)(g_Xb + (size_t)b * RPB * NCOLS);

    float acc[16];
#pragma unroll
    for (int i = 0; i < 16; i++) acc[i] = 0.f;

    // prologue: 5 chunk loads in flight
#pragma unroll
    for (int c = 0; c < 5; c++) prefetch_chunk(x_s, c, Xb + (size_t)c * CHUNK_U4, t);

    // invn = 1/||y|| from 32 partials (warp 0, hidden under prefetch latency)
    if (w == 0) {
        float s = g_ss[it * REDB + lane];
#pragma unroll
        for (int o = 16; o > 0; o >>= 1) s += __shfl_down_sync(0xffffffffu, s, o);
        if (lane == 0) s_invn = rsqrtf(s);
    }

    asm volatile("cp.async.wait_group 4;\n" ::: "memory");
    __syncthreads();
    float invn = s_invn;
    {
        float a0 = p1_dot(x_s, yv, lane, w);
        if (lane == 0) upart[0][w] = a0;
    }

    for (int k = 0; k < NCHUNK; k++) {
        if (k + 1 < NCHUNK) {
            if (k + 4 < NCHUNK) {
                asm volatile("cp.async.wait_group 3;\n" ::: "memory");
            } else {
                asm volatile("cp.async.wait_group 0;\n" ::: "memory");
            }
        }
        __syncthreads();

        if (k + 5 < NCHUNK)
            prefetch_chunk(x_s, (k + 5) % NBUF, Xb + (size_t)(k + 5) * CHUNK_U4, t);

        if (k + 1 < NCHUNK) {
            float a0 = p1_dot(x_s + ((k + 1) % NBUF) * CHUNK_U4, yv, lane, w);
            if (lane == 0) upart[(k + 1) & 1][w] = a0;
        }

        // phase2(chunk k)
        {
            const float* up = upart[k & 1];
            float u0 = invn * (((up[0] + up[1]) + (up[2] + up[3]))
                             + ((up[4] + up[5]) + (up[6] + up[7])));
            const uint4* x0 = x_s + (k % NBUF) * CHUNK_U4 + t;
#pragma unroll
            for (int j = 0; j < 2; j++) {
                uint4 xb = x0[256 * j];
                float2 f0 = __bfloat1622float2(*(__nv_bfloat162*)&xb.x);
                float2 f1 = __bfloat1622float2(*(__nv_bfloat162*)&xb.y);
                float2 f2 = __bfloat1622float2(*(__nv_bfloat162*)&xb.z);
                float2 f3 = __bfloat1622float2(*(__nv_bfloat162*)&xb.w);
                acc[8 * j + 0] += f0.x * u0; acc[8 * j + 1] += f0.y * u0;
                acc[8 * j + 2] += f1.x * u0; acc[8 * j + 3] += f1.y * u0;
                acc[8 * j + 4] += f2.x * u0; acc[8 * j + 5] += f2.y * u0;
                acc[8 * j + 6] += f3.x * u0; acc[8 * j + 7] += f3.y * u0;
            }
        }
    }

    // epilogue: write w partials + alpha partial
    float d = 0.f;
    float4* wp = (float4*)(g_wpart + (size_t)b * NCOLS);
#pragma unroll
    for (int j = 0; j < 2; j++) {
#pragma unroll
        for (int h = 0; h < 2; h++) {
            int fi = j * 512 + 2 * t + h;
            float4 av = make_float4(acc[8 * j + 4 * h + 0], acc[8 * j + 4 * h + 1],
                                    acc[8 * j + 4 * h + 2], acc[8 * j + 4 * h + 3]);
            wp[fi] = av;
            float4 vv = __ldg(&yv[fi]);
            d += av.x * vv.x + av.y * vv.y + av.z * vv.z + av.w * vv.w;
        }
    }
    red[t] = d;
    __syncthreads();
    for (int s = 128; s > 0; s >>= 1) {
        if (t < s) red[t] += red[t + s];
        __syncthreads();
    }
    if (t == 0) g_dot[b] = red[0] * invn;

    // ---- publish and take ticket ----
    __threadfence();
    __syncthreads();
    if (t == 0) s_ticket = atomicAdd(&g_ctr[it], 1);
    __syncthreads();
    int ticket = s_ticket;
    if (ticket < NBLK - REDB) return;          // early finishers exit
    int rb = ticket - (NBLK - REDB);           // reducer slot 0..31

    // ---- wait for all blocks (all CTAs co-resident: 3/SM x 148 >= 256) ----
    if (t == 0) {
        while (atomicAdd(&g_ctr[it], 0) < NBLK) { }
    }
    __syncthreads();
    __threadfence();

    // ---- reduce 128 columns (32 float4 groups) for this slot ----
    int cgl = lane;                 // 0..31 f4-group within slot
    int slice = w;                  // 0..7, each sums 32 of 256 partials
    int cg = rb * 32 + cgl;         // global f4-group
    float4 wsum = make_float4(0.f, 0.f, 0.f, 0.f);
    {
        const float4* wpr = (const float4*)g_wpart + cg;
#pragma unroll
        for (int i = 0; i < 32; i++) {
            float4 v = wpr[(size_t)(slice * 32 + i) * (NCOLS / 4)];
            wsum.x += v.x; wsum.y += v.y; wsum.z += v.z; wsum.w += v.w;
        }
    }
    sp[slice][cgl] = wsum;

    // scalars: warp 0 -> alpha, warp 1 -> cur norm, warp 2 -> prev norm
    if (w == 0) {
        float dv = 0.f;
#pragma unroll
        for (int i = 0; i < 8; i++) dv += g_dot[lane + 32 * i];
#pragma unroll
        for (int o = 16; o > 0; o >>= 1) dv += __shfl_down_sync(0xffffffffu, dv, o);
        if (lane == 0) s_scal[0] = dv;
    } else if (w == 1) {
        float nv = g_ss[it * REDB + lane];
#pragma unroll
        for (int o = 16; o > 0; o >>= 1) nv += __shfl_down_sync(0xffffffffu, nv, o);
        if (lane == 0) s_scal[1] = nv;
    } else if (w == 2) {
        float nv = (it > 0) ? g_ss[(it - 1) * REDB + lane] : 0.f;
#pragma unroll
        for (int o = 16; o > 0; o >>= 1) nv += __shfl_down_sync(0xffffffffu, nv, o);
        if (lane == 0) s_scal[2] = nv;
    }
    __syncthreads();

    // slice tree (fixed order)
    for (int s = 4; s > 0; s >>= 1) {
        if (slice < s) {
            float4 o = sp[slice + s][cgl];
            sp[slice][cgl].x += o.x; sp[slice][cgl].y += o.y;
            sp[slice][cgl].z += o.z; sp[slice][cgl].w += o.w;
        }
        __syncthreads();
    }

    if (w == 0) {   // 32 threads: one f4-group each
        float alpha = s_scal[0];
        float n = sqrtf(s_scal[1]);
        float ca = alpha / n;
        float cb = (it > 0) ? n * rsqrtf(s_scal[2]) : 0.f;

        float4 wv = sp[0][cgl];
        const float4* ycur = (const float4*)(g_y + (it % 3) * NCOLS);
        const float4* yprv = (const float4*)(g_y + ((it + 2) % 3) * NCOLS);
        float4* ynxt = (float4*)(g_y + ((it + 1) % 3) * NCOLS);
        float4 vc = ycur[cg], vp4 = yprv[cg];
        float4 yt;
        yt.x = wv.x - ca * vc.x - cb * vp4.x;
        yt.y = wv.y - ca * vc.y - cb * vp4.y;
        yt.z = wv.z - ca * vc.z - cb * vp4.z;
        yt.w = wv.w - ca * vc.w - cb * vp4.w;
        ynxt[cg] = yt;

        float nrm = yt.x * yt.x + yt.y * yt.y + yt.z * yt.z + yt.w * yt.w;
#pragma unroll
        for (int o = 16; o > 0; o >>= 1) nrm += __shfl_down_sync(0xffffffffu, nrm, o);
        if (lane == 0) {
            g_ss[(it + 1) * REDB + rb] = nrm;
            if (rb == 0) g_alpha[it] = alpha;
        }
    }
}

// ---------------- lambda_max of tridiagonal: warp-parallel Sturm bisection (fp64) ----------------
__global__ void k_tridiag(float* out) {
    __shared__ double a[T_ITERS], b2[T_ITERS];
    int lane = threadIdx.x;
    for (int i = lane; i < T_ITERS; i += 32) {
        a[i] = (double)g_alpha[i];
        double s = 0.0;
        if (i > 0) {
            for (int p = 0; p < REDB; p++) s += (double)g_ss[i * REDB + p];
        }
        b2[i] = s;
    }
    __syncwarp();

    double lo = 1e300, hi = -1e300;
    for (int i = lane; i < T_ITERS; i += 32) {
        double r = sqrt(b2[i]) + ((i + 1 < T_ITERS) ? sqrt(b2[i + 1]) : 0.0);
        lo = fmin(lo, a[i] - r);
        hi = fmax(hi, a[i] + r);
    }
#pragma unroll
    for (int o = 16; o > 0; o >>= 1) {
        lo = fmin(lo, __shfl_xor_sync(0xffffffffu, lo, o));
        hi = fmax(hi, __shfl_xor_sync(0xffffffffu, hi, o));
    }
    lo -= 1.0; hi += 1.0;

    for (int round = 0; round < 6; round++) {
        double wdt = (hi - lo) / 33.0;
        double x = lo + wdt * (double)(lane + 1);
        int cnt = 0;
        double d = a[0] - x;
        if (d == 0.0) d = -1e-300;
        if (d < 0.0) cnt++;
        for (int i = 1; i < T_ITERS; i++) {
            d = a[i] - x - b2[i] / d;
            if (d == 0.0) d = -1e-300;
            if (d < 0.0) cnt++;
        }
        unsigned m = __ballot_sync(0xffffffffu, cnt >= T_ITERS);
        if (m) {
            int f = __ffs(m) - 1;
            hi = lo + wdt * (double)(f + 1);
            lo = lo + wdt * (double)f;
        } else {
            lo = lo + wdt * 32.0;
        }
    }
    if (lane == 0) out[0] = (float)(0.5 * (lo + hi));
}

// ---------------- launch ----------------
extern "C" void kernel_launch(void* const* d_in, const int* in_sizes, int n_in,
                              void* d_out, int out_size) {
    const float* X = (const float*)d_in[0];
    float* out = (float*)d_out;

    cudaFuncSetAttribute(k_matvec, cudaFuncAttributeMaxDynamicSharedMemorySize, SMEM_BYTES);

    k_tobf16<<<8192, 256>>>(X);
    k_init<<<1, 1024>>>();
    for (int it = 0; it < T_ITERS; it++) {
        k_matvec<<<NBLK, 256, SMEM_BYTES>>>(it);
    }
    k_tridiag<<<1, 32>>>(out);
}